// round 5
// baseline (speedup 1.0000x reference)
#include <cuda_runtime.h>

#define B 16
#define NA 65536
#define NG 32
#define IOU_BLKS 64      // per image: 64 blocks x 256 threads x 4 anchors
#define CAP 16384

// ---------------- scratch (device globals; zero at module load) ----------------
__device__ unsigned long long g_spart[B * IOU_BLKS * NG];  // per-block per-gt packed max
__device__ float        g_neg[B * NA];
__device__ unsigned int g_hcnt[B * 2048];   // K1 atomics; K2 consumes then re-zeroes
__device__ float        g_hsum[B * 2048];   // per-bin value sums (float atomics)
__device__ int   g_np[B];
__device__ float g_loc[B];
__device__ float g_pos[B];
__device__ float g_cf[B];
__device__ float g_locf[B];
__device__ int   g_npf[B];
__device__ unsigned int g_done;

__device__ __forceinline__ float sl1(float x) {
    float ax = fabsf(x);
    return ax < 1.f ? 0.5f * ax * ax : ax - 0.5f;
}

// ---------------- K1: IoU + per-anchor loss + count/sum hist ----------------
__global__ __launch_bounds__(256) void k_main(const float4* __restrict__ bbox,
                                              const float* __restrict__ conf,
                                              const float4* __restrict__ anchors,
                                              const float4* __restrict__ gt) {
    __shared__ float4 sgt[NG];
    __shared__ float sarea[NG];
    __shared__ unsigned long long sp[8][NG];
    __shared__ unsigned int shist[2048];
    __shared__ float ssumS[2048];
    __shared__ int s_np; __shared__ float s_loc, s_pos;

    int tid = threadIdx.x, lane = tid & 31, wid = tid >> 5;
    int b = blockIdx.x >> 6, blk = blockIdx.x & 63;
    int abase = blk * 1024 + tid * 4;

    for (int i = tid; i < 2048; i += 256) { shist[i] = 0; ssumS[i] = 0.f; }
    if (tid < NG) {
        float4 g = gt[b * NG + tid];
        sgt[tid] = g;
        sarea[tid] = (g.z - g.x) * (g.w - g.y);
    }
    if (tid == 0) { s_np = 0; s_loc = 0.f; s_pos = 0.f; }
    __syncthreads();

    float4 an[4]; float ar[4], best[4]; int bg[4];
    const float4* ap = anchors + b * NA + abase;
#pragma unroll
    for (int j = 0; j < 4; j++) {
        an[j] = ap[j];
        ar[j] = (an[j].z - an[j].x) * (an[j].w - an[j].y);
        best[j] = -1.f; bg[j] = 0;
    }

#pragma unroll 1
    for (int g = 0; g < NG; g++) {
        float4 gb = sgt[g];
        float sa = sarea[g];
        float gmax = -1.f; int gidx = 0;
#pragma unroll
        for (int j = 0; j < 4; j++) {
            float lx = fmaxf(an[j].x, gb.x), ly = fmaxf(an[j].y, gb.y);
            float rx = fminf(an[j].z, gb.z), ry = fminf(an[j].w, gb.w);
            float w = fmaxf(rx - lx, 0.f), h = fmaxf(ry - ly, 0.f);
            float inter = w * h;
            float q = __fdividef(inter, (ar[j] + sa) - inter);
            if (q > best[j]) { best[j] = q; bg[j] = g; }   // first max = lowest g
            if (q > gmax) { gmax = q; gidx = j; }          // first max = lowest anchor
        }
        unsigned bits = __float_as_uint(gmax);
        unsigned m = __reduce_max_sync(0xffffffffu, bits);
        unsigned ball = __ballot_sync(0xffffffffu, bits == m);
        if (lane == (__ffs(ball) - 1))
            sp[wid][g] = ((unsigned long long)m << 32) | (unsigned)(~(abase + gidx));
    }

    float4 cf4 = *(const float4*)(conf + b * NA + abase);
    float pv[4] = {cf4.x, cf4.y, cf4.z, cf4.w};
    float ng[4];
    int npl = 0; float locl = 0.f, posl = 0.f;
#pragma unroll
    for (int j = 0; j < 4; j++) {
        if (best[j] > 0.5f) {
            ng[j] = 0.f;
            posl += -__logf(pv[j]);
            float4 bp = bbox[b * NA + abase + j];
            float4 m = sgt[bg[j]];
            float d0 = (bp.x + bp.z) * 0.5f - (m.x + m.z) * 0.5f;
            float d1 = (bp.y + bp.w) * 0.5f - (m.y + m.w) * 0.5f;
            float d2 = (bp.z - bp.x) - (m.z - m.x);
            float d3 = (bp.w - bp.y) - (m.w - m.y);
            locl += sl1(d0) + sl1(d1) + sl1(d2) + sl1(d3);
            npl++;
        } else {
            ng[j] = fmaxf(-__logf(1.0f - pv[j]), 0.0f);
        }
        unsigned key = __float_as_uint(ng[j]) >> 21;
        atomicAdd(&shist[key], 1u);
        atomicAdd(&ssumS[key], ng[j]);
    }
    *(float4*)(g_neg + b * NA + abase) = make_float4(ng[0], ng[1], ng[2], ng[3]);
    if (npl) { atomicAdd(&s_np, npl); atomicAdd(&s_loc, locl); atomicAdd(&s_pos, posl); }
    __syncthreads();

    for (int i = tid; i < 2048; i += 256) {
        unsigned c = shist[i];
        if (c) {
            atomicAdd(&g_hcnt[b * 2048 + i], c);
            atomicAdd(&g_hsum[b * 2048 + i], ssumS[i]);
        }
    }
    if (tid < NG) {
        unsigned long long m = sp[0][tid];
#pragma unroll
        for (int w = 1; w < 8; w++) { unsigned long long v = sp[w][tid]; if (v > m) m = v; }
        g_spart[(b * IOU_BLKS + blk) * NG + tid] = m;
    }
    if (tid == 0 && s_np) {
        atomicAdd(&g_np[b], s_np);
        atomicAdd(&g_loc[b], s_loc);
        atomicAdd(&g_pos[b], s_pos);
    }
}

// ---------------- K2: corrections + exact top-k + final ----------------
__device__ double blockReduceD(double v, double* sred) {
    __syncthreads();
#pragma unroll
    for (int o = 16; o; o >>= 1) v += __shfl_down_sync(0xffffffffu, v, o);
    int w = threadIdx.x >> 5, l = threadIdx.x & 31;
    if (l == 0) sred[w] = v;
    __syncthreads();
    if (threadIdx.x < 32) {
        v = sred[threadIdx.x];
#pragma unroll
        for (int o = 16; o; o >>= 1) v += __shfl_down_sync(0xffffffffu, v, o);
    }
    return v;   // valid on tid 0
}

extern __shared__ float dbuf[];   // 2*CAP floats

__global__ __launch_bounds__(1024) void k_sel(const float4* __restrict__ bbox,
                                              const float* __restrict__ conf,
                                              const float4* __restrict__ anchors,
                                              const float4* __restrict__ gt,
                                              float* __restrict__ out) {
    __shared__ float4 sgt[NG];
    __shared__ float sarea[NG];
    __shared__ unsigned scnt[2048];
    __shared__ float ssum[2048];
    __shared__ unsigned long long s_gmax[NG];
    __shared__ int s_af[NG];
    __shared__ unsigned h128[128];
    __shared__ float s128f[128];
    __shared__ int s_n, s_sel;
    __shared__ unsigned s_kk;
    __shared__ double sred[32];
    __shared__ double s_acc;
    __shared__ int s_npc; __shared__ float s_locc, s_posc;
    __shared__ int s_gnp; __shared__ float s_gloc, s_gpos;

    int b = blockIdx.x, tid = threadIdx.x;
    int lane = tid & 31, wrp = tid >> 5;

    if (tid < NG) {
        float4 g = gt[b * NG + tid];
        sgt[tid] = g;
        sarea[tid] = (g.z - g.x) * (g.w - g.y);
        s_gmax[tid] = 0ull;
    }
    if (tid == 0) {
        s_npc = 0; s_locc = 0.f; s_posc = 0.f; s_acc = 0.0; s_n = 0; s_sel = 0; s_kk = 0;
        s_gnp = g_np[b]; s_gloc = g_loc[b]; s_gpos = g_pos[b];
        g_np[b] = 0; g_loc[b] = 0.f; g_pos[b] = 0.f;
    }
    scnt[tid]        = g_hcnt[b * 2048 + tid];
    scnt[tid + 1024] = g_hcnt[b * 2048 + tid + 1024];
    ssum[tid]        = g_hsum[b * 2048 + tid];
    ssum[tid + 1024] = g_hsum[b * 2048 + tid + 1024];
    g_hcnt[b * 2048 + tid] = 0;
    g_hcnt[b * 2048 + tid + 1024] = 0;
    g_hsum[b * 2048 + tid] = 0.f;
    g_hsum[b * 2048 + tid + 1024] = 0.f;
    __syncthreads();

    // parallel reduce of forced-anchor partials: 2048 u64, coalesced
    {
        unsigned long long v0 = g_spart[(size_t)b * 2048 + tid];
        unsigned long long v1 = g_spart[(size_t)b * 2048 + tid + 1024];
        atomicMax(&s_gmax[tid & 31], v0);
        atomicMax(&s_gmax[(tid + 1024) & 31], v1);
    }
    __syncthreads();
    if (tid < NG) s_af[tid] = (int)(~(unsigned)(s_gmax[tid] & 0xffffffffull));
    __syncthreads();

    // corrections: warp w handles forced anchor of gt w; lanes = 32 gts in parallel
    {
        int af = s_af[wrp];
        unsigned dup = __ballot_sync(0xffffffffu, lane < wrp && s_af[lane] == af);
        if (dup == 0) {
            float4 an = anchors[b * NA + af];
            float area_a = (an.z - an.x) * (an.w - an.y);
            float4 gb = sgt[lane];
            float lx = fmaxf(an.x, gb.x), ly = fmaxf(an.y, gb.y);
            float rx = fminf(an.z, gb.z), ry = fminf(an.w, gb.w);
            float w = fmaxf(rx - lx, 0.f), h = fmaxf(ry - ly, 0.f);
            float inter = w * h;
            float q = __fdividef(inter, (area_a + sarea[lane]) - inter);  // bit-identical to K1
            unsigned bits = __float_as_uint(q);
            unsigned m = __reduce_max_sync(0xffffffffu, bits);
            unsigned ball = __ballot_sync(0xffffffffu, bits == m);
            int bgi = __ffs(ball) - 1;
            float bestq = __uint_as_float(m);
            if (!(bestq > 0.5f) && lane == 0) {
                int idx = b * NA + af;
                float old = g_neg[idx];
                g_neg[idx] = 0.f;
                unsigned ob = __float_as_uint(old) >> 21;
                atomicSub(&scnt[ob], 1u);
                atomicAdd(&ssum[ob], -old);
                atomicAdd(&scnt[0], 1u);
                float p = conf[idx];
                float4 bp = bbox[idx];
                float4 mg = sgt[bgi];
                float d0 = (bp.x + bp.z) * 0.5f - (mg.x + mg.z) * 0.5f;
                float d1 = (bp.y + bp.w) * 0.5f - (mg.y + mg.w) * 0.5f;
                float d2 = (bp.z - bp.x) - (mg.z - mg.x);
                float d3 = (bp.w - bp.y) - (mg.w - mg.y);
                atomicAdd(&s_npc, 1);
                atomicAdd(&s_locc, sl1(d0) + sl1(d1) + sl1(d2) + sl1(d3));
                atomicAdd(&s_posc, -__logf(p));
            }
        }
    }
    __syncthreads();

    int np = s_gnp + s_npc;
    float posn = (s_gpos + s_posc) / (float)max(np, 1);
    float locim = s_gloc + s_locc;
    int kn = min(3 * np, NA - np);
    unsigned kk0 = (unsigned)max(kn, 1);

    // suffix-inclusive scan of 2048 counts (in-place; ssum preserved)
    for (int off = 1; off < 2048; off <<= 1) {
        unsigned a0 = (tid + off < 2048) ? scnt[tid + off] : 0u;
        unsigned a1 = (tid + 1024 + off < 2048) ? scnt[tid + 1024 + off] : 0u;
        __syncthreads();
        scnt[tid] += a0; scnt[tid + 1024] += a1;
        __syncthreads();
    }
    {
        unsigned incl0 = scnt[tid], excl0 = scnt[tid + 1];
        if (excl0 < kk0 && kk0 <= incl0) { s_sel = tid; s_kk = kk0 - excl0; }
        int i1 = tid + 1024;
        unsigned incl1 = scnt[i1], excl1 = (i1 < 2047) ? scnt[i1 + 1] : 0u;
        if (excl1 < kk0 && kk0 <= incl1) { s_sel = i1; s_kk = kk0 - excl1; }
    }
    __syncthreads();
    int sel = s_sel;
    unsigned kk = s_kk;

    // sum of fully-included bins from bin sums (no per-element arithmetic)
    {
        double dv = 0.0;
        if (tid > sel) dv += (double)ssum[tid];
        if (tid + 1024 > sel) dv += (double)ssum[tid + 1024];
        double r = blockReduceD(dv, sred);
        if (tid == 0) s_acc += r;
    }
    __syncthreads();

    // compare-only scan: compact boundary bin with warp-aggregated atomics, MLP via unroll
    const float4* neg4 = (const float4*)(g_neg + b * NA);
#pragma unroll
    for (int ii = 0; ii < 16; ii++) {
        int i = tid + ii * 1024;
        float4 v = neg4[i];
        float vv[4] = {v.x, v.y, v.z, v.w};
#pragma unroll
        for (int c = 0; c < 4; c++) {
            bool hit = ((__float_as_uint(vv[c]) >> 21) == (unsigned)sel);
            unsigned ball = __ballot_sync(0xffffffffu, hit);
            if (ball) {
                int leader = __ffs(ball) - 1;
                int basep = 0;
                if (lane == leader) basep = atomicAdd(&s_n, __popc(ball));
                basep = __shfl_sync(0xffffffffu, basep, leader);
                int rank = __popc(ball & ((1u << lane) - 1u));
                if (hit && basep + rank < CAP) dbuf[basep + rank] = vv[c];
            }
        }
    }
    __syncthreads();

    int count_sel = s_n;
    bool ovf = count_sel > CAP;
    float* cur = dbuf; float* nxt = dbuf + CAP;
    int curn = ovf ? 0 : count_sel;
    unsigned pref = (unsigned)sel;

#pragma unroll 1
    for (int shift = 14; shift >= 0; shift -= 7) {
        if (!ovf && kk == (unsigned)curn) {          // take-all fast path
            double as = 0.0;
            for (int i = tid; i < curn; i += 1024) as += (double)cur[i];
            double rr = blockReduceD(as, sred);
            if (tid == 0) s_acc += rr;
            kk = 0;
            break;
        }
        if (tid < 128) { h128[tid] = 0u; s128f[tid] = 0.f; }
        __syncthreads();
        if (!ovf) {
            for (int i = tid; i < curn; i += 1024) {
                float v = cur[i];
                unsigned key = (__float_as_uint(v) >> shift) & 127u;
                atomicAdd(&h128[key], 1u);
                atomicAdd(&s128f[key], v);
            }
        } else {
            for (int i = tid; i < NA / 4; i += 1024) {
                float4 v = neg4[i];
                float vv[4] = {v.x, v.y, v.z, v.w};
#pragma unroll
                for (int c = 0; c < 4; c++) {
                    unsigned bits = __float_as_uint(vv[c]);
                    if ((bits >> (shift + 7)) == pref) {
                        atomicAdd(&h128[(bits >> shift) & 127u], 1u);
                        atomicAdd(&s128f[(bits >> shift) & 127u], vv[c]);
                    }
                }
            }
        }
        __syncthreads();
        for (int off = 1; off < 128; off <<= 1) {
            unsigned a = 0;
            if (tid < 128 && tid + off < 128) a = h128[tid + off];
            __syncthreads();
            if (tid < 128) h128[tid] += a;
            __syncthreads();
        }
        if (tid < 128) {
            unsigned incl = h128[tid], excl = (tid < 127) ? h128[tid + 1] : 0u;
            if (excl < kk && kk <= incl) { s_sel = tid; s_kk = kk - excl; }
        }
        if (tid == 0) s_n = 0;
        __syncthreads();
        int sel2 = s_sel;
        int nextcnt = (int)(h128[sel2] - ((sel2 < 127) ? h128[sel2 + 1] : 0u));
        bool fits = nextcnt <= CAP;

        double dv = (tid < 128 && tid > sel2) ? (double)s128f[tid] : 0.0;
        double rr = blockReduceD(dv, sred);
        if (tid == 0) s_acc += rr;
        __syncthreads();

        if (shift > 0) {
            if (!ovf) {
                for (int i = tid; i < curn; i += 1024) {
                    float v2 = cur[i];
                    if (((__float_as_uint(v2) >> shift) & 127u) == (unsigned)sel2)
                        nxt[atomicAdd(&s_n, 1)] = v2;
                }
            } else if (fits) {
                for (int i = tid; i < NA / 4; i += 1024) {
                    float4 v = neg4[i];
                    float vv[4] = {v.x, v.y, v.z, v.w};
#pragma unroll
                    for (int c = 0; c < 4; c++) {
                        unsigned bits = __float_as_uint(vv[c]);
                        if ((bits >> (shift + 7)) == pref &&
                            ((bits >> shift) & 127u) == (unsigned)sel2)
                            cur[atomicAdd(&s_n, 1)] = vv[c];
                    }
                }
            }
            __syncthreads();
            kk = s_kk;
            if (!ovf) {
                curn = s_n;
                float* t = cur; cur = nxt; nxt = t;
            } else if (fits) {
                ovf = false;
                curn = s_n;
            }
        } else {
            kk = s_kk;
        }
        pref = (pref << 7) | (unsigned)sel2;
        __syncthreads();
    }

    if (tid == 0) {
        double negloss = s_acc + (double)kk * (double)__uint_as_float(pref);
        g_cf[b]   = posn + (float)(negloss / (double)max(kn, 1));
        g_locf[b] = locim;
        g_npf[b]  = np;
        __threadfence();
        unsigned t = atomicAdd(&g_done, 1u);
        if (t == B - 1) {
            g_done = 0;
            __threadfence();
            float cs = 0.f, ls = 0.f; int ns = 0;
#pragma unroll
            for (int i = 0; i < B; i++) {
                cs += __ldcg(&g_cf[i]);
                ls += __ldcg(&g_locf[i]);
                ns += __ldcg(&g_npf[i]);
            }
            out[0] = ls / (float)max(ns, 1) + cs / (float)B;
        }
    }
}

// ---------------- entry ----------------
extern "C" void kernel_launch(void* const* d_in, const int* in_sizes, int n_in,
                              void* d_out, int out_size) {
    const float4* bbox    = (const float4*)d_in[0];
    const float*  conf    = (const float*)d_in[1];
    const float4* anchors = (const float4*)d_in[2];
    const float4* gt      = (const float4*)d_in[3];

    cudaFuncSetAttribute(k_sel, cudaFuncAttributeMaxDynamicSharedMemorySize,
                         2 * CAP * (int)sizeof(float));

    k_main<<<B * IOU_BLKS, 256>>>(bbox, conf, anchors, gt);
    k_sel<<<B, 1024, 2 * CAP * sizeof(float)>>>(bbox, conf, anchors, gt, (float*)d_out);
}

// round 6
// speedup vs baseline: 1.0188x; 1.0188x over previous
#include <cuda_runtime.h>

#define B 16
#define NA 65536
#define NG 32
#define IOU_BLKS 64      // per image: 64 blocks x 256 threads x 4 anchors
#define SCAN_BLKS 16
#define CAP 16384

// ---------------- scratch (device globals; zero at module load) ----------------
__device__ unsigned long long g_spart[B * IOU_BLKS * NG];
__device__ float        g_neg[B * NA];
__device__ unsigned int g_hcnt[B * 2048];   // K1 atomics; k_corr consumes + re-zeroes
__device__ int   g_np[B];
__device__ float g_loc[B];
__device__ float g_pos[B];
// k_corr outputs
__device__ int      g_sel[B];
__device__ unsigned g_kkv[B];
__device__ float    g_posn[B];
__device__ int      g_knv[B];
__device__ int      g_candn[B];
// k_scan outputs
__device__ double g_part[B * SCAN_BLKS];
__device__ float  g_cand[B * CAP];
// finals
__device__ float g_cf[B];
__device__ float g_locf[B];
__device__ int   g_npf[B];
__device__ unsigned g_done;

__device__ __forceinline__ float sl1(float x) {
    float ax = fabsf(x);
    return ax < 1.f ? 0.5f * ax * ax : ax - 0.5f;
}

// ---------------- K1: IoU + per-anchor loss + count hist (R4 structure) ----------------
__global__ __launch_bounds__(256) void k_main(const float4* __restrict__ bbox,
                                              const float* __restrict__ conf,
                                              const float4* __restrict__ anchors,
                                              const float4* __restrict__ gt) {
    __shared__ float4 sgt[NG];
    __shared__ float sarea[NG];
    __shared__ unsigned long long sp[8][NG];
    __shared__ unsigned int shist[2048];
    __shared__ int s_np; __shared__ float s_loc, s_pos;

    int tid = threadIdx.x, lane = tid & 31, wid = tid >> 5;
    int b = blockIdx.x >> 6, blk = blockIdx.x & 63;
    int abase = blk * 1024 + tid * 4;

    for (int i = tid; i < 2048; i += 256) shist[i] = 0;
    if (tid < NG) {
        float4 g = gt[b * NG + tid];
        sgt[tid] = g;
        sarea[tid] = (g.z - g.x) * (g.w - g.y);
    }
    if (tid == 0) { s_np = 0; s_loc = 0.f; s_pos = 0.f; }
    __syncthreads();

    float4 an[4]; float ar[4], best[4]; int bg[4];
    const float4* ap = anchors + b * NA + abase;
#pragma unroll
    for (int j = 0; j < 4; j++) {
        an[j] = ap[j];
        ar[j] = (an[j].z - an[j].x) * (an[j].w - an[j].y);
        best[j] = -1.f; bg[j] = 0;
    }

#pragma unroll 2
    for (int g = 0; g < NG; g++) {
        float4 gb = sgt[g];
        float sa = sarea[g];
        float gmax = -1.f; int gidx = 0;
#pragma unroll
        for (int j = 0; j < 4; j++) {
            float lx = fmaxf(an[j].x, gb.x), ly = fmaxf(an[j].y, gb.y);
            float rx = fminf(an[j].z, gb.z), ry = fminf(an[j].w, gb.w);
            float w = fmaxf(rx - lx, 0.f), h = fmaxf(ry - ly, 0.f);
            float inter = w * h;
            float q = __fdividef(inter, (ar[j] + sa) - inter);
            if (q > best[j]) { best[j] = q; bg[j] = g; }   // first max = lowest g
            if (q > gmax) { gmax = q; gidx = j; }          // first max = lowest anchor
        }
        unsigned bits = __float_as_uint(gmax);
        unsigned m = __reduce_max_sync(0xffffffffu, bits);
        unsigned ball = __ballot_sync(0xffffffffu, bits == m);
        if (lane == (__ffs(ball) - 1))
            sp[wid][g] = ((unsigned long long)m << 32) | (unsigned)(~(abase + gidx));
    }

    float4 cf4 = *(const float4*)(conf + b * NA + abase);
    float pv[4] = {cf4.x, cf4.y, cf4.z, cf4.w};
    float ng[4];
    int npl = 0; float locl = 0.f, posl = 0.f;
#pragma unroll
    for (int j = 0; j < 4; j++) {
        if (best[j] > 0.5f) {
            ng[j] = 0.f;
            posl += -__logf(pv[j]);
            float4 bp = bbox[b * NA + abase + j];
            float4 m = sgt[bg[j]];
            float d0 = (bp.x + bp.z) * 0.5f - (m.x + m.z) * 0.5f;
            float d1 = (bp.y + bp.w) * 0.5f - (m.y + m.w) * 0.5f;
            float d2 = (bp.z - bp.x) - (m.z - m.x);
            float d3 = (bp.w - bp.y) - (m.w - m.y);
            locl += sl1(d0) + sl1(d1) + sl1(d2) + sl1(d3);
            npl++;
        } else {
            ng[j] = fmaxf(-__logf(1.0f - pv[j]), 0.0f);
        }
        atomicAdd(&shist[__float_as_uint(ng[j]) >> 21], 1u);
    }
    *(float4*)(g_neg + b * NA + abase) = make_float4(ng[0], ng[1], ng[2], ng[3]);
    if (npl) { atomicAdd(&s_np, npl); atomicAdd(&s_loc, locl); atomicAdd(&s_pos, posl); }
    __syncthreads();

    for (int i = tid; i < 2048; i += 256) {
        unsigned c = shist[i];
        if (c) atomicAdd(&g_hcnt[b * 2048 + i], c);
    }
    if (tid < NG) {
        unsigned long long m = sp[0][tid];
#pragma unroll
        for (int w = 1; w < 8; w++) { unsigned long long v = sp[w][tid]; if (v > m) m = v; }
        g_spart[(b * IOU_BLKS + blk) * NG + tid] = m;
    }
    if (tid == 0 && s_np) {
        atomicAdd(&g_np[b], s_np);
        atomicAdd(&g_loc[b], s_loc);
        atomicAdd(&g_pos[b], s_pos);
    }
}

// ---------------- K2: per-image corrections + bin select ----------------
__global__ __launch_bounds__(1024) void k_corr(const float4* __restrict__ bbox,
                                               const float* __restrict__ conf,
                                               const float4* __restrict__ anchors,
                                               const float4* __restrict__ gt) {
    __shared__ float4 sgt[NG];
    __shared__ float sarea[NG];
    __shared__ unsigned scnt[2048];
    __shared__ unsigned long long s_gmax[NG];
    __shared__ int s_af[NG];
    __shared__ int s_npc; __shared__ float s_locc, s_posc;
    __shared__ int s_sel; __shared__ unsigned s_kk;

    int b = blockIdx.x, tid = threadIdx.x;
    int lane = tid & 31, wrp = tid >> 5;

    if (tid < NG) {
        float4 g = gt[b * NG + tid];
        sgt[tid] = g;
        sarea[tid] = (g.z - g.x) * (g.w - g.y);
        s_gmax[tid] = 0ull;
    }
    if (tid == 0) { s_npc = 0; s_locc = 0.f; s_posc = 0.f; s_sel = 0; s_kk = 1; }
    scnt[tid]        = g_hcnt[b * 2048 + tid];
    scnt[tid + 1024] = g_hcnt[b * 2048 + tid + 1024];
    g_hcnt[b * 2048 + tid] = 0;
    g_hcnt[b * 2048 + tid + 1024] = 0;
    __syncthreads();

    // parallel reduce of forced-anchor partials: 2048 u64, coalesced
    {
        unsigned long long v0 = g_spart[(size_t)b * 2048 + tid];
        unsigned long long v1 = g_spart[(size_t)b * 2048 + tid + 1024];
        atomicMax(&s_gmax[tid & 31], v0);
        atomicMax(&s_gmax[(tid + 1024) & 31], v1);
    }
    __syncthreads();
    if (tid < NG) s_af[tid] = (int)(~(unsigned)(s_gmax[tid] & 0xffffffffull));
    __syncthreads();

    // corrections: warp w handles forced anchor of gt w
    {
        int af = s_af[wrp];
        unsigned dup = __ballot_sync(0xffffffffu, lane < wrp && s_af[lane] == af);
        if (dup == 0) {
            float4 an = anchors[b * NA + af];
            float area_a = (an.z - an.x) * (an.w - an.y);
            float4 gb = sgt[lane];
            float lx = fmaxf(an.x, gb.x), ly = fmaxf(an.y, gb.y);
            float rx = fminf(an.z, gb.z), ry = fminf(an.w, gb.w);
            float w = fmaxf(rx - lx, 0.f), h = fmaxf(ry - ly, 0.f);
            float inter = w * h;
            float q = __fdividef(inter, (area_a + sarea[lane]) - inter);  // bit-identical to K1
            unsigned bits = __float_as_uint(q);
            unsigned m = __reduce_max_sync(0xffffffffu, bits);
            unsigned ball = __ballot_sync(0xffffffffu, bits == m);
            int bgi = __ffs(ball) - 1;
            float bestq = __uint_as_float(m);
            if (!(bestq > 0.5f) && lane == 0) {
                int idx = b * NA + af;
                float old = g_neg[idx];
                g_neg[idx] = 0.f;
                atomicSub(&scnt[__float_as_uint(old) >> 21], 1u);
                atomicAdd(&scnt[0], 1u);
                float p = conf[idx];
                float4 bp = bbox[idx];
                float4 mg = sgt[bgi];
                float d0 = (bp.x + bp.z) * 0.5f - (mg.x + mg.z) * 0.5f;
                float d1 = (bp.y + bp.w) * 0.5f - (mg.y + mg.w) * 0.5f;
                float d2 = (bp.z - bp.x) - (mg.z - mg.x);
                float d3 = (bp.w - bp.y) - (mg.w - mg.y);
                atomicAdd(&s_npc, 1);
                atomicAdd(&s_locc, sl1(d0) + sl1(d1) + sl1(d2) + sl1(d3));
                atomicAdd(&s_posc, -__logf(p));
            }
        }
    }
    __syncthreads();

    int np = g_np[b] + s_npc;
    float posn = (g_pos[b] + s_posc) / (float)max(np, 1);
    float locim = g_loc[b] + s_locc;
    int kn = min(3 * np, NA - np);

    // suffix-inclusive scan of 2048 counts
    for (int off = 1; off < 2048; off <<= 1) {
        unsigned a0 = (tid + off < 2048) ? scnt[tid + off] : 0u;
        unsigned a1 = (tid + 1024 + off < 2048) ? scnt[tid + 1024 + off] : 0u;
        __syncthreads();
        scnt[tid] += a0; scnt[tid + 1024] += a1;
        __syncthreads();
    }
    unsigned kk0 = (unsigned)max(kn, 1);
    {
        unsigned incl0 = scnt[tid], excl0 = scnt[tid + 1];
        if (excl0 < kk0 && kk0 <= incl0) { s_sel = tid; s_kk = kk0 - excl0; }
        int i1 = tid + 1024;
        unsigned incl1 = scnt[i1], excl1 = (i1 < 2047) ? scnt[i1 + 1] : 0u;
        if (excl1 < kk0 && kk0 <= incl1) { s_sel = i1; s_kk = kk0 - excl1; }
    }
    __syncthreads();

    if (tid == 0) {
        g_np[b] = 0; g_loc[b] = 0.f; g_pos[b] = 0.f;   // clean for next replay
        g_candn[b] = 0;
        g_posn[b] = posn;
        g_locf[b] = locim;
        g_npf[b]  = np;
        g_knv[b]  = kn;
        if (kn <= 0) {
            g_sel[b] = -1;
            g_cf[b] = posn;
        } else {
            g_sel[b] = s_sel;
            g_kkv[b] = s_kk;
        }
    }
}

// ---------------- K3: parallel scan — sum-above + candidate compaction ----------------
__global__ __launch_bounds__(256) void k_scan() {
    __shared__ double sredS[8];
    int blk = blockIdx.x;
    int b = blk >> 4, seg = blk & 15;
    int tid = threadIdx.x;
    int sel = g_sel[b];

    float acc = 0.f;
    if (sel >= 0) {
        const float4* p4 = (const float4*)(g_neg + b * NA) + seg * 1024;
        float* cand = g_cand + b * CAP;
#pragma unroll
        for (int ii = 0; ii < 4; ii++) {
            float4 v = p4[tid + ii * 256];
            float vv[4] = {v.x, v.y, v.z, v.w};
#pragma unroll
            for (int c = 0; c < 4; c++) {
                int key = (int)(__float_as_uint(vv[c]) >> 21);
                if (key > sel) acc += vv[c];
                else if (key == sel) {
                    int p = atomicAdd(&g_candn[b], 1);
                    if (p < CAP) cand[p] = vv[c];
                }
            }
        }
    }
    // block reduce (double)
    double d = (double)acc;
#pragma unroll
    for (int o = 16; o; o >>= 1) d += __shfl_down_sync(0xffffffffu, d, o);
    if ((tid & 31) == 0) sredS[tid >> 5] = d;
    __syncthreads();
    if (tid == 0) {
        double t = 0.0;
#pragma unroll
        for (int w = 0; w < 8; w++) t += sredS[w];
        g_part[b * SCAN_BLKS + seg] = t;
    }
}

// ---------------- K4: radix select over candidates + final ----------------
__device__ double blockReduceD(double v, double* sred) {
    __syncthreads();
#pragma unroll
    for (int o = 16; o; o >>= 1) v += __shfl_down_sync(0xffffffffu, v, o);
    int w = threadIdx.x >> 5, l = threadIdx.x & 31;
    if (l == 0) sred[w] = v;
    __syncthreads();
    if (threadIdx.x < 32) {
        v = sred[threadIdx.x];
#pragma unroll
        for (int o = 16; o; o >>= 1) v += __shfl_down_sync(0xffffffffu, v, o);
    }
    return v;   // valid on tid 0
}

extern __shared__ float dbuf[];   // 2*CAP floats

__global__ __launch_bounds__(1024) void k_fin(float* __restrict__ out) {
    __shared__ unsigned h128[128];
    __shared__ float s128f[128];
    __shared__ int s_n, s_sel;
    __shared__ unsigned s_kk;
    __shared__ double sred[32];
    __shared__ double s_acc;

    int b = blockIdx.x, tid = threadIdx.x;
    int sel = g_sel[b];

    if (sel >= 0) {
        // combine scan partials
        double pv = (tid < SCAN_BLKS) ? g_part[b * SCAN_BLKS + tid] : 0.0;
        double r = blockReduceD(pv, sred);
        if (tid == 0) { s_acc = r; s_n = 0; }
        __syncthreads();

        int cn = g_candn[b];
        unsigned kk = g_kkv[b];
        int kn = g_knv[b];
        float posn = g_posn[b];

        bool ovf = cn > CAP;
        int curn = ovf ? 0 : cn;
        float* cur = dbuf; float* nxt = dbuf + CAP;
        // load candidates into smem
        if (!ovf)
            for (int i = tid; i < curn; i += 1024) cur[i] = g_cand[b * CAP + i];
        __syncthreads();

        const float4* neg4 = (const float4*)(g_neg + b * NA);
        unsigned pref = (unsigned)sel;

#pragma unroll 1
        for (int shift = 14; shift >= 0; shift -= 7) {
            if (!ovf && kk == (unsigned)curn) {          // take-all fast path
                float as = 0.f;
                for (int i = tid; i < curn; i += 1024) as += cur[i];
                double rr = blockReduceD((double)as, sred);
                if (tid == 0) s_acc += rr;
                kk = 0;
                break;
            }
            if (tid < 128) { h128[tid] = 0u; s128f[tid] = 0.f; }
            __syncthreads();
            if (!ovf) {
                for (int i = tid; i < curn; i += 1024) {
                    float v = cur[i];
                    unsigned key = (__float_as_uint(v) >> shift) & 127u;
                    atomicAdd(&h128[key], 1u);
                    atomicAdd(&s128f[key], v);
                }
            } else {
                for (int i = tid; i < NA / 4; i += 1024) {
                    float4 v = neg4[i];
                    float vv[4] = {v.x, v.y, v.z, v.w};
#pragma unroll
                    for (int c = 0; c < 4; c++) {
                        unsigned bits = __float_as_uint(vv[c]);
                        if ((bits >> (shift + 7)) == pref) {
                            atomicAdd(&h128[(bits >> shift) & 127u], 1u);
                            atomicAdd(&s128f[(bits >> shift) & 127u], vv[c]);
                        }
                    }
                }
            }
            __syncthreads();
            for (int off = 1; off < 128; off <<= 1) {
                unsigned a = 0;
                if (tid < 128 && tid + off < 128) a = h128[tid + off];
                __syncthreads();
                if (tid < 128) h128[tid] += a;
                __syncthreads();
            }
            if (tid < 128) {
                unsigned incl = h128[tid], excl = (tid < 127) ? h128[tid + 1] : 0u;
                if (excl < kk && kk <= incl) { s_sel = tid; s_kk = kk - excl; }
            }
            if (tid == 0) s_n = 0;
            __syncthreads();
            int sel2 = s_sel;
            int nextcnt = (int)(h128[sel2] - ((sel2 < 127) ? h128[sel2 + 1] : 0u));
            bool fits = nextcnt <= CAP;

            double dv = (tid < 128 && tid > sel2) ? (double)s128f[tid] : 0.0;
            double rr = blockReduceD(dv, sred);
            if (tid == 0) s_acc += rr;
            __syncthreads();

            if (shift > 0) {
                if (!ovf) {
                    for (int i = tid; i < curn; i += 1024) {
                        float v2 = cur[i];
                        if (((__float_as_uint(v2) >> shift) & 127u) == (unsigned)sel2)
                            nxt[atomicAdd(&s_n, 1)] = v2;
                    }
                } else if (fits) {
                    for (int i = tid; i < NA / 4; i += 1024) {
                        float4 v = neg4[i];
                        float vv[4] = {v.x, v.y, v.z, v.w};
#pragma unroll
                        for (int c = 0; c < 4; c++) {
                            unsigned bits = __float_as_uint(vv[c]);
                            if ((bits >> (shift + 7)) == pref &&
                                ((bits >> shift) & 127u) == (unsigned)sel2)
                                cur[atomicAdd(&s_n, 1)] = vv[c];
                        }
                    }
                }
                __syncthreads();
                kk = s_kk;
                if (!ovf) {
                    curn = s_n;
                    float* t = cur; cur = nxt; nxt = t;
                } else if (fits) {
                    ovf = false;
                    curn = s_n;
                }
            } else {
                kk = s_kk;
            }
            pref = (pref << 7) | (unsigned)sel2;
            __syncthreads();
        }

        if (tid == 0) {
            double negloss = s_acc + (double)kk * (double)__uint_as_float(pref);
            g_cf[b] = posn + (float)(negloss / (double)max(kn, 1));
        }
    }
    __syncthreads();

    if (tid == 0) {
        __threadfence();
        unsigned t = atomicAdd(&g_done, 1u);
        if (t == B - 1) {
            g_done = 0;
            __threadfence();
            float cs = 0.f, ls = 0.f; int ns = 0;
#pragma unroll
            for (int i = 0; i < B; i++) {
                cs += __ldcg(&g_cf[i]);
                ls += __ldcg(&g_locf[i]);
                ns += __ldcg(&g_npf[i]);
            }
            out[0] = ls / (float)max(ns, 1) + cs / (float)B;
        }
    }
}

// ---------------- entry ----------------
extern "C" void kernel_launch(void* const* d_in, const int* in_sizes, int n_in,
                              void* d_out, int out_size) {
    const float4* bbox    = (const float4*)d_in[0];
    const float*  conf    = (const float*)d_in[1];
    const float4* anchors = (const float4*)d_in[2];
    const float4* gt      = (const float4*)d_in[3];

    cudaFuncSetAttribute(k_fin, cudaFuncAttributeMaxDynamicSharedMemorySize,
                         2 * CAP * (int)sizeof(float));

    k_main<<<B * IOU_BLKS, 256>>>(bbox, conf, anchors, gt);
    k_corr<<<B, 1024>>>(bbox, conf, anchors, gt);
    k_scan<<<B * SCAN_BLKS, 256>>>();
    k_fin<<<B, 1024, 2 * CAP * sizeof(float)>>>((float*)d_out);
}